// round 6
// baseline (speedup 1.0000x reference)
#include <cuda_runtime.h>
#include <cuda_bf16.h>
#include <float.h>
#include <math.h>

// Problem constants (from reference)
#define H 512
#define W 512
#define PSIZE 4
#define NEUR 32
#define TOPK 4
#define S2 16
#define NH 509            // (512 - 3) / 1
#define NW 509
#define NZ (NH * NW)      // 259081
#define EPSV 1e-8f

// One warp per patch z; lane n = neuron n.
//
// Numerics: replicate XLA's lowering bit-exactly so the top-4 selection
// matches the reference on every row (one flipped row already exceeds the
// 1e-3 rel-err budget):
//   * einsum 'znd,zd->zn' is strength-reduced by XLA to reduce(multiply)
//     inside a loop fusion -> ROUNDED MUL then ROUNDED ADD (no FMA),
//     sequential ascending over d, init 0.
//   * norm = sqrt(reduce(x*x)): same -- rounded square, sequential rounded
//     adds ascending.
//   * den = sqrt(acc) + eps (rounded add); elements divided by den BEFORE
//     the dot (rounded div, per element).
// All ops via __f*_rn intrinsics: correctly rounded and immune to both
// --use_fast_math and FP contraction.
__global__ __launch_bounds__(256)
void topk_layer2d_kernel(const float* __restrict__ x,
                         const float* __restrict__ Wz,
                         float* __restrict__ out)
{
    const int lane = threadIdx.x & 31;
    const int z    = blockIdx.x * (blockDim.x >> 5) + (threadIdx.x >> 5);
    if (z >= NZ) return;

    const int r = z / NW;
    const int c = z - r * NW;

    // ---- weight row: 4 independent float4 loads (front-batched, MLP=4) ----
    const float4* wp = reinterpret_cast<const float4*>(
        Wz + ((size_t)z * NEUR + (size_t)lane) * S2);
    float4 w0 = wp[0];
    float4 w1 = wp[1];
    float4 w2 = wp[2];
    float4 w3 = wp[3];

    float w[S2];
    w[0]=w0.x;  w[1]=w0.y;  w[2]=w0.z;  w[3]=w0.w;
    w[4]=w1.x;  w[5]=w1.y;  w[6]=w1.z;  w[7]=w1.w;
    w[8]=w2.x;  w[9]=w2.y;  w[10]=w2.z; w[11]=w2.w;
    w[12]=w3.x; w[13]=w3.y; w[14]=w3.z; w[15]=w3.w;

    // ---- patch (uniform-address broadcast loads, L1-resident) ----
    float p[S2];
#pragma unroll
    for (int a = 0; a < PSIZE; a++)
#pragma unroll
        for (int b = 0; b < PSIZE; b++)
            p[a * PSIZE + b] = __ldg(&x[(r + a) * W + (c + b)]);

    // ---- patch norm: rounded square + sequential rounded add, ascending ----
    float pacc = 0.f;
#pragma unroll
    for (int d = 0; d < S2; d++)
        pacc = __fadd_rn(pacc, __fmul_rn(p[d], p[d]));
    const float pden = __fadd_rn(__fsqrt_rn(pacc), EPSV);

    // pn is warp-uniform: lane d (<16) performs the single rounded division
    // for element d; the dot loop reads it via shuffle (identical bits to
    // every lane dividing itself, at 1/16th the cost).
    const unsigned FULL = 0xFFFFFFFFu;
    const float pn_mine = (lane < S2) ? __fdiv_rn(p[lane], pden) : 0.f;

    // ---- weight norm: same emission pattern ----
    float wacc = 0.f;
#pragma unroll
    for (int d = 0; d < S2; d++)
        wacc = __fadd_rn(wacc, __fmul_rn(w[d], w[d]));
    const float wden = __fadd_rn(__fsqrt_rn(wacc), EPSV);

    // ---- pre = reduce(mul): rounded mul, rounded add, ascending ----
    float acc = 0.f;
#pragma unroll
    for (int d = 0; d < S2; d++) {
        const float pn_d = __shfl_sync(FULL, pn_mine, d);
        const float wn_d = __fdiv_rn(w[d], wden);
        acc = __fadd_rn(acc, __fmul_rn(wn_d, pn_d));
    }
    const float pre = acc;

    // ---- top-4 threshold across the 32 lanes ----
    // 4 rounds: warp max-reduce, retire exactly one max-holding lane
    // (lowest lane on ties) -> thr == sorted_desc[3] with multiplicity,
    // identical to jax.lax.top_k's K-th value.
    float thr = -FLT_MAX;
    bool alive = true;
#pragma unroll
    for (int k = 0; k < TOPK; k++) {
        float m = alive ? pre : -FLT_MAX;
#pragma unroll
        for (int off = 16; off > 0; off >>= 1)
            m = fmaxf(m, __shfl_xor_sync(FULL, m, off));
        thr = m;
        unsigned ball = __ballot_sync(FULL, alive && (pre == m));
        if (lane == (int)__ffs(ball) - 1) alive = false;
    }

    // coalesced 128B store per warp
    out[(size_t)z * NEUR + lane] = (pre >= thr) ? pre : 0.f;
}

extern "C" void kernel_launch(void* const* d_in, const int* in_sizes, int n_in,
                              void* d_out, int out_size)
{
    const float* x  = (const float*)d_in[0];   // (512, 512) fp32
    const float* Wz = (const float*)d_in[1];   // (NZ, 32, 16) fp32
    float* out = (float*)d_out;                // (NZ, 32) fp32

    const int WARPS_PER_BLOCK = 8;             // 256 threads
    const int blocks = (NZ + WARPS_PER_BLOCK - 1) / WARPS_PER_BLOCK;
    topk_layer2d_kernel<<<blocks, WARPS_PER_BLOCK * 32>>>(x, Wz, out);
}